// round 8
// baseline (speedup 1.0000x reference)
#include <cuda_runtime.h>
#include <math.h>
#include <stdint.h>

// ---------------------------------------------------------------------------
// Problem constants
// ---------------------------------------------------------------------------
constexpr int E     = 256;
constexpr int BATCH = 512;
constexpr int NNEG  = 2048;
constexpr int K2    = 512;           // expanded GEMM K

// Fragment-packed scratch:
//  g_A: [mAtom=32][kAtom=64][lane=32][4]   (A' = [b^2 | -2ab], tf32-rounded)
//  g_T: [nAtom=256][kAtom=64][lane=32][2]  (T' = [t^2 | t],   tf32-rounded)
__device__ float g_A[BATCH * K2];
__device__ float g_T[NNEG  * K2];
__device__ float g_alpha[BATCH];     // sum a^2

__device__ __forceinline__ float to_tf32(float x) {
    uint32_t u;
    asm("cvt.rna.tf32.f32 %0, %1;" : "=r"(u) : "f"(x));
    return __uint_as_float(u);
}
__device__ __forceinline__ uint32_t smem_u32(const void* p) {
    uint32_t a;
    asm("{ .reg .u64 t; cvta.to.shared.u64 t, %1; cvt.u32.u64 %0, t; }" : "=r"(a) : "l"(p));
    return a;
}

#define CP_ASYNC16(sm, gp) \
    asm volatile("cp.async.cg.shared.global [%0], [%1], 16;" :: "r"(sm), "l"(gp) : "memory")
#define CP_COMMIT() asm volatile("cp.async.commit_group;" ::: "memory")
#define CP_WAIT(n)  asm volatile("cp.async.wait_group %0;" :: "n"(n) : "memory")

// mma.m16n8k8 tf32 fragment scatter helpers (row i / tail row j, logical col k)
__device__ __forceinline__ void putA(int i, int k, float v) {
    int idx = (((i >> 4) * 64 + (k >> 3)) * 32 + (((i & 7) << 2) | (k & 3))) * 4
            + ((((k >> 2) & 1) << 1) | ((i >> 3) & 1));
    g_A[idx] = v;
}
__device__ __forceinline__ void putT(int j, int k, float v) {
    int idx = (((j >> 3) * 64 + (k >> 3)) * 32 + (((j & 7) << 2) | (k & 3))) * 2
            + ((k >> 2) & 1);
    g_T[idx] = v;
}

// ---------------------------------------------------------------------------
// Prep: warp-per-row; writes fragment-packed layouts.
// ---------------------------------------------------------------------------
__global__ __launch_bounds__(256) void prep_kernel(const float* __restrict__ head,
                                                   const float* __restrict__ tail,
                                                   const float* __restrict__ rel,
                                                   const int*   __restrict__ rid) {
    const int warp = blockIdx.x * 8 + (threadIdx.x >> 5);
    const int lane = threadIdx.x & 31;
    const int e0 = lane * 4;
    const int e1 = lane * 4 + 128;
    int kk[8] = {e0, e0 + 1, e0 + 2, e0 + 3, e1, e1 + 1, e1 + 2, e1 + 3};

    if (warp < BATCH) {
        const int i = warp;
        float4 h0 = *reinterpret_cast<const float4*>(&head[i * E + e0]);
        float4 h1 = *reinterpret_cast<const float4*>(&head[i * E + e1]);
        float ss = h0.x*h0.x + h0.y*h0.y + h0.z*h0.z + h0.w*h0.w
                 + h1.x*h1.x + h1.y*h1.y + h1.z*h1.z + h1.w*h1.w;
        #pragma unroll
        for (int o = 16; o > 0; o >>= 1) ss += __shfl_xor_sync(0xffffffffu, ss, o);
        float inv = 1.0f / fmaxf(sqrtf(ss), 1e-12f);

        int r = rid[i];
        const float* rrow = &rel[(long)r * (2 * E)];
        float4 rh0 = *reinterpret_cast<const float4*>(&rrow[e0]);
        float4 rh1 = *reinterpret_cast<const float4*>(&rrow[e1]);
        float4 rt0 = *reinterpret_cast<const float4*>(&rrow[E + e0]);
        float4 rt1 = *reinterpret_cast<const float4*>(&rrow[E + e1]);

        float a[8], b[8];
        a[0]=(h0.x*inv)*rh0.x; a[1]=(h0.y*inv)*rh0.y; a[2]=(h0.z*inv)*rh0.z; a[3]=(h0.w*inv)*rh0.w;
        a[4]=(h1.x*inv)*rh1.x; a[5]=(h1.y*inv)*rh1.y; a[6]=(h1.z*inv)*rh1.z; a[7]=(h1.w*inv)*rh1.w;
        b[0]=rt0.x; b[1]=rt0.y; b[2]=rt0.z; b[3]=rt0.w;
        b[4]=rt1.x; b[5]=rt1.y; b[6]=rt1.z; b[7]=rt1.w;

        float asq = 0.0f;
        #pragma unroll
        for (int q = 0; q < 8; q++) asq += a[q] * a[q];
        #pragma unroll
        for (int o = 16; o > 0; o >>= 1) asq += __shfl_xor_sync(0xffffffffu, asq, o);
        if (lane == 0) g_alpha[i] = asq;

        #pragma unroll
        for (int q = 0; q < 8; q++) {
            putA(i, kk[q],       to_tf32(b[q] * b[q]));          // [b^2 | ...]
            putA(i, kk[q] + 256, to_tf32(-2.0f * a[q] * b[q]));  // [... | -2ab]
        }
    } else if (warp < BATCH + NNEG) {
        const int j = warp - BATCH;
        float4 t0 = *reinterpret_cast<const float4*>(&tail[j * E + e0]);
        float4 t1 = *reinterpret_cast<const float4*>(&tail[j * E + e1]);
        float ss = t0.x*t0.x + t0.y*t0.y + t0.z*t0.z + t0.w*t0.w
                 + t1.x*t1.x + t1.y*t1.y + t1.z*t1.z + t1.w*t1.w;
        #pragma unroll
        for (int o = 16; o > 0; o >>= 1) ss += __shfl_xor_sync(0xffffffffu, ss, o);
        float inv = 1.0f / fmaxf(sqrtf(ss), 1e-12f);

        float t[8] = {t0.x*inv, t0.y*inv, t0.z*inv, t0.w*inv,
                      t1.x*inv, t1.y*inv, t1.z*inv, t1.w*inv};
        #pragma unroll
        for (int q = 0; q < 8; q++) {
            putT(j, kk[q],       to_tf32(t[q] * t[q]));   // [t^2 | ...]
            putT(j, kk[q] + 256, to_tf32(t[q]));          // [... | t]
        }
    }
}

// ---------------------------------------------------------------------------
// Main: tf32 mma.sync GEMM on fragment-packed operands.
// CTA tile 64x128 (4 mAtoms x 16 nAtoms), 8 warps (2x4), warp tile 32x32.
// K=512 in 16 chunks of 32 (4 kAtoms). 3-stage cp.async pipeline.
// Fragment loads: LDS.128 (A), LDS.64 (B) — conflict-free, contiguous.
// ---------------------------------------------------------------------------
constexpr int BK_ATOMS = 4;                       // kAtoms per chunk (BK=32)
constexpr int NCHUNK   = 16;
constexpr int NSTAGE   = 3;
constexpr int A_WORDS  = 4 * BK_ATOMS * 32 * 4;   // 2048 (4 mAtoms)
constexpr int B_WORDS  = 16 * BK_ATOMS * 32 * 2;  // 4096 (16 nAtoms)
constexpr int BUF_WORDS = A_WORDS + B_WORDS;      // 6144 (24 KB)
constexpr int SMEM_BYTES = NSTAGE * BUF_WORDS * 4; // 73728

__device__ __forceinline__ void mma_tf32(float d[4], const uint32_t a[4], const uint32_t b[2]) {
    asm volatile(
        "mma.sync.aligned.m16n8k8.row.col.f32.tf32.tf32.f32 "
        "{%0,%1,%2,%3}, {%4,%5,%6,%7}, {%8,%9}, {%0,%1,%2,%3};"
        : "+f"(d[0]), "+f"(d[1]), "+f"(d[2]), "+f"(d[3])
        : "r"(a[0]), "r"(a[1]), "r"(a[2]), "r"(a[3]), "r"(b[0]), "r"(b[1]));
}

__global__ __launch_bounds__(256, 1) void pairre_mma_kernel(float* __restrict__ out) {
    extern __shared__ __align__(16) float smem[];
    const uint32_t sb = smem_u32(smem);

    const int tid  = threadIdx.x;
    const int wid  = tid >> 5;
    const int lane = tid & 31;
    const int ib  = blockIdx.y * 64;
    const int jb  = blockIdx.x * 128;
    const int ibA = blockIdx.y * 4;      // first mAtom
    const int jbA = blockIdx.x * 16;     // first nAtom

    const int wmA = (wid >> 2) * 2;      // warp's first mAtom (0/2)
    const int wnA = (wid & 3) * 4;       // warp's first nAtom (0..12)
    const int g   = lane >> 2;
    const int t   = lane & 3;

    float d[2][4][4];
    #pragma unroll
    for (int ma = 0; ma < 2; ma++)
        #pragma unroll
        for (int na = 0; na < 4; na++)
            #pragma unroll
            for (int q = 0; q < 4; q++)
                d[ma][na][q] = 0.0f;

    auto issue_chunk = [&](int c, int stage) {
        const uint32_t bufA = sb + (stage * BUF_WORDS) * 4;
        const uint32_t bufB = bufA + A_WORDS * 4;
        // A: 4 mAtom segments of 512 contiguous floats (128 float4)
        #pragma unroll
        for (int p = 0; p < 2; p++) {
            int f4i = tid + p * 256;          // 0..511
            int m   = f4i >> 7;               // mAtom-in-tile
            int off = (f4i & 127) * 4;        // float offset in segment
            CP_ASYNC16(bufA + (m * 512 + off) * 4,
                       &g_A[((ibA + m) * 64 + 4 * c) * 128 + off]);
        }
        // B: 16 nAtom segments of 256 contiguous floats (64 float4)
        #pragma unroll
        for (int p = 0; p < 4; p++) {
            int f4i = tid + p * 256;          // 0..1023
            int nA  = f4i >> 6;
            int off = (f4i & 63) * 4;
            CP_ASYNC16(bufB + (nA * 256 + off) * 4,
                       &g_T[((jbA + nA) * 64 + 4 * c) * 64 + off]);
        }
        CP_COMMIT();
    };

    issue_chunk(0, 0);
    issue_chunk(1, 1);

    for (int c = 0; c < NCHUNK; c++) {
        if (c + 1 < NCHUNK) { CP_WAIT(1); } else { CP_WAIT(0); }
        __syncthreads();
        if (c + 2 < NCHUNK) issue_chunk(c + 2, (c + 2) % NSTAGE);

        const int stage = c % NSTAGE;
        const float* SA = smem + stage * BUF_WORDS;
        const float* SB = SA + A_WORDS;

        #pragma unroll
        for (int ks = 0; ks < BK_ATOMS; ks++) {
            uint32_t afr[2][4], bfr[4][2];
            #pragma unroll
            for (int ma = 0; ma < 2; ma++) {
                float4 v = *reinterpret_cast<const float4*>(
                    &SA[((wmA + ma) * BK_ATOMS + ks) * 128 + lane * 4]);
                afr[ma][0] = __float_as_uint(v.x);
                afr[ma][1] = __float_as_uint(v.y);
                afr[ma][2] = __float_as_uint(v.z);
                afr[ma][3] = __float_as_uint(v.w);
            }
            #pragma unroll
            for (int na = 0; na < 4; na++) {
                float2 v = *reinterpret_cast<const float2*>(
                    &SB[((wnA + na) * BK_ATOMS + ks) * 64 + lane * 2]);
                bfr[na][0] = __float_as_uint(v.x);
                bfr[na][1] = __float_as_uint(v.y);
            }
            #pragma unroll
            for (int ma = 0; ma < 2; ma++)
                #pragma unroll
                for (int na = 0; na < 4; na++)
                    mma_tf32(d[ma][na], afr[ma], bfr[na]);
        }
    }

    // Epilogue: out[i,j] = -sqrt(max(d + alpha_i, 0))
    #pragma unroll
    for (int ma = 0; ma < 2; ma++) {
        const int i0 = ib + (wmA + ma) * 16 + g;
        const float al0 = g_alpha[i0];
        const float al1 = g_alpha[i0 + 8];
        #pragma unroll
        for (int na = 0; na < 4; na++) {
            const int j = jb + (wnA + na) * 8 + t * 2;
            float2 v0, v1;
            v0.x = -sqrtf(fmaxf(d[ma][na][0] + al0, 0.0f));
            v0.y = -sqrtf(fmaxf(d[ma][na][1] + al0, 0.0f));
            v1.x = -sqrtf(fmaxf(d[ma][na][2] + al1, 0.0f));
            v1.y = -sqrtf(fmaxf(d[ma][na][3] + al1, 0.0f));
            *reinterpret_cast<float2*>(&out[i0 * NNEG + j])       = v0;
            *reinterpret_cast<float2*>(&out[(i0 + 8) * NNEG + j]) = v1;
        }
    }
}

// ---------------------------------------------------------------------------
// Launch
// ---------------------------------------------------------------------------
extern "C" void kernel_launch(void* const* d_in, const int* in_sizes, int n_in,
                              void* d_out, int out_size) {
    const float* head = (const float*)d_in[0];   // (512, 256)
    const float* tail = (const float*)d_in[1];   // (1, 2048, 256)
    const float* rel  = (const float*)d_in[2];   // (1000, 512)
    const int*   rid  = (const int*)d_in[3];     // (512,) int32 on the wire
    float* out = (float*)d_out;                  // (512, 2048)

    cudaFuncSetAttribute(pairre_mma_kernel,
                         cudaFuncAttributeMaxDynamicSharedMemorySize, SMEM_BYTES);

    prep_kernel<<<(BATCH + NNEG) / 8, 256>>>(head, tail, rel, rid);

    dim3 grid(NNEG / 128, BATCH / 64);   // (16, 8) = 128 CTAs
    pairre_mma_kernel<<<grid, 256, SMEM_BYTES>>>(out);
}

// round 9
// speedup vs baseline: 1.1102x; 1.1102x over previous
#include <cuda_runtime.h>
#include <math.h>
#include <stdint.h>

// ---------------------------------------------------------------------------
// Problem constants
// ---------------------------------------------------------------------------
constexpr int E     = 256;
constexpr int BATCH = 512;
constexpr int NNEG  = 2048;
constexpr int K2    = 512;           // expanded GEMM K

// Fragment-packed scratch:
//  g_A: [mAtom=32][kAtom=64][lane=32][4]   (A' = [b^2 | -2ab], tf32-rounded)
//  g_T: [nAtom=256][kAtom=64][lane=32][2]  (T' = [t^2 | t],   tf32-rounded)
__device__ float g_A[BATCH * K2];
__device__ float g_T[NNEG  * K2];
__device__ float g_alpha[BATCH];     // sum a^2

__device__ __forceinline__ float to_tf32(float x) {
    uint32_t u;
    asm("cvt.rna.tf32.f32 %0, %1;" : "=r"(u) : "f"(x));
    return __uint_as_float(u);
}
__device__ __forceinline__ uint32_t smem_u32(const void* p) {
    uint32_t a;
    asm("{ .reg .u64 t; cvta.to.shared.u64 t, %1; cvt.u32.u64 %0, t; }" : "=r"(a) : "l"(p));
    return a;
}

#define CP_ASYNC16(sm, gp) \
    asm volatile("cp.async.cg.shared.global [%0], [%1], 16;" :: "r"(sm), "l"(gp) : "memory")
#define CP_COMMIT() asm volatile("cp.async.commit_group;" ::: "memory")
#define CP_WAIT(n)  asm volatile("cp.async.wait_group %0;" :: "n"(n) : "memory")

// ---------------------------------------------------------------------------
// Prep with coalesced packed writes.
//  blocks 0..31    : head mAtoms (16 rows each)
//  blocks 32..287  : tail nAtoms (8 rows each)
// Stage rows in smem, then emit fragment-packed blocks with consecutive
// addresses per warp (inverse fragment map).
// ---------------------------------------------------------------------------
constexpr int PITCH = 258;   // smem row pitch (floats), de-conflicts packed-read phase

__global__ __launch_bounds__(256) void prep_kernel(const float* __restrict__ head,
                                                   const float* __restrict__ tail,
                                                   const float* __restrict__ rel,
                                                   const int*   __restrict__ rid) {
    __shared__ float sa[16 * PITCH];   // head: a rows   | tail: t rows (8 used)
    __shared__ float sbv[16 * PITCH];  // head: b rows

    const int tid = threadIdx.x;

    if (blockIdx.x < 32) {
        // ------------------- head mAtom block: rows m0*16 .. +15 -------------------
        const int m0 = blockIdx.x;
        const int ty = tid >> 4;      // row 0..15
        const int tx = tid & 15;
        const int i  = m0 * 16 + ty;

        float h[16];
        float ss = 0.0f;
        #pragma unroll
        for (int q = 0; q < 16; q++) {
            h[q] = head[i * E + q * 16 + tx];
            ss += h[q] * h[q];
        }
        #pragma unroll
        for (int o = 8; o > 0; o >>= 1) ss += __shfl_xor_sync(0xffffffffu, ss, o);
        float inv = 1.0f / fmaxf(sqrtf(ss), 1e-12f);

        const int r = rid[i];
        const float* rrow = &rel[(long)r * (2 * E)];
        float asq = 0.0f;
        #pragma unroll
        for (int q = 0; q < 16; q++) {
            int k = q * 16 + tx;
            float a = (h[q] * inv) * rrow[k];
            float b = rrow[E + k];
            sa [ty * PITCH + k] = a;
            sbv[ty * PITCH + k] = b;
            asq += a * a;
        }
        #pragma unroll
        for (int o = 8; o > 0; o >>= 1) asq += __shfl_xor_sync(0xffffffffu, asq, o);
        if (tx == 0) g_alpha[i] = asq;
        __syncthreads();

        // packed write: 64 kAtoms x 128 floats, consecutive tid -> consecutive addr
        #pragma unroll
        for (int p = 0; p < 32; p++) {
            int idx   = tid + p * 256;       // 0..8191
            int kAtom = idx >> 7;            // 0..63
            int o     = idx & 127;
            int lane  = o >> 2, reg = o & 3;
            int i_loc = ((reg & 1) << 3) | (lane >> 2);
            int kl    = ((kAtom & 31) << 3) | ((reg >> 1) << 2) | (lane & 3);
            float v;
            if (kAtom < 32) {
                float b = sbv[i_loc * PITCH + kl];
                v = to_tf32(b * b);
            } else {
                float a = sa [i_loc * PITCH + kl];
                float b = sbv[i_loc * PITCH + kl];
                v = to_tf32(-2.0f * a * b);
            }
            g_A[(m0 * 64 + kAtom) * 128 + o] = v;
        }
    } else {
        // ------------------- tail nAtom block: rows n0*8 .. +7 -------------------
        const int n0 = blockIdx.x - 32;
        const int ty = tid >> 5;      // row 0..7 (one warp per row)
        const int tx = tid & 31;
        const int j  = n0 * 8 + ty;

        float t[8];
        float ss = 0.0f;
        #pragma unroll
        for (int q = 0; q < 8; q++) {
            t[q] = tail[j * E + q * 32 + tx];
            ss += t[q] * t[q];
        }
        #pragma unroll
        for (int o = 16; o > 0; o >>= 1) ss += __shfl_xor_sync(0xffffffffu, ss, o);
        float inv = 1.0f / fmaxf(sqrtf(ss), 1e-12f);

        #pragma unroll
        for (int q = 0; q < 8; q++)
            sa[ty * PITCH + q * 32 + tx] = t[q] * inv;
        __syncthreads();

        // packed write: 64 kAtoms x 64 floats
        #pragma unroll
        for (int p = 0; p < 16; p++) {
            int idx   = tid + p * 256;       // 0..4095
            int kAtom = idx >> 6;            // 0..63
            int o     = idx & 63;
            int lane  = o >> 1, reg = o & 1;
            int j_loc = lane >> 2;
            int kl    = ((kAtom & 31) << 3) | (reg << 2) | (lane & 3);
            float tv  = sa[j_loc * PITCH + kl];
            float v   = (kAtom < 32) ? to_tf32(tv * tv) : to_tf32(tv);
            g_T[(n0 * 64 + kAtom) * 64 + o] = v;
        }
    }
}

// ---------------------------------------------------------------------------
// Main: tf32 mma.sync GEMM on fragment-packed operands.
// CTA tile 64x128 (4 mAtoms x 16 nAtoms), 512 threads, 16 warps as 4x4,
// warp tile 16x32 (1 mAtom x 4 nAtoms). 3-stage cp.async pipeline.
// ---------------------------------------------------------------------------
constexpr int BK_ATOMS = 4;                        // kAtoms per chunk (BK=32)
constexpr int NCHUNK   = 16;
constexpr int NSTAGE   = 3;
constexpr int A_WORDS  = 4 * BK_ATOMS * 32 * 4;    // 2048
constexpr int B_WORDS  = 16 * BK_ATOMS * 32 * 2;   // 4096
constexpr int BUF_WORDS = A_WORDS + B_WORDS;       // 6144 (24 KB)
constexpr int SMEM_BYTES = NSTAGE * BUF_WORDS * 4; // 73728

__device__ __forceinline__ void mma_tf32(float d[4], const uint32_t a[4], const uint32_t b[2]) {
    asm volatile(
        "mma.sync.aligned.m16n8k8.row.col.f32.tf32.tf32.f32 "
        "{%0,%1,%2,%3}, {%4,%5,%6,%7}, {%8,%9}, {%0,%1,%2,%3};"
        : "+f"(d[0]), "+f"(d[1]), "+f"(d[2]), "+f"(d[3])
        : "r"(a[0]), "r"(a[1]), "r"(a[2]), "r"(a[3]), "r"(b[0]), "r"(b[1]));
}

__global__ __launch_bounds__(512, 1) void pairre_mma_kernel(float* __restrict__ out) {
    extern __shared__ __align__(16) float smem[];
    const uint32_t sb = smem_u32(smem);

    const int tid  = threadIdx.x;
    const int wid  = tid >> 5;
    const int lane = tid & 31;
    const int ib  = blockIdx.y * 64;
    const int jb  = blockIdx.x * 128;
    const int ibA = blockIdx.y * 4;      // first mAtom
    const int jbA = blockIdx.x * 16;     // first nAtom

    const int wmA = wid >> 2;            // warp's mAtom (0..3)
    const int wnA = (wid & 3) * 4;       // warp's first nAtom (0..12)
    const int g   = lane >> 2;
    const int t   = lane & 3;

    float d[4][4];
    #pragma unroll
    for (int na = 0; na < 4; na++)
        #pragma unroll
        for (int q = 0; q < 4; q++)
            d[na][q] = 0.0f;

    auto issue_chunk = [&](int c, int stage) {
        const uint32_t bufA = sb + (stage * BUF_WORDS) * 4;
        const uint32_t bufB = bufA + A_WORDS * 4;
        // A: 512 float4 (4 mAtom segments of 512 floats) — 1 per thread
        {
            int m   = tid >> 7;
            int off = (tid & 127) * 4;
            CP_ASYNC16(bufA + (m * 512 + off) * 4,
                       &g_A[((ibA + m) * 64 + 4 * c) * 128 + off]);
        }
        // B: 1024 float4 (16 nAtom segments of 256 floats) — 2 per thread
        #pragma unroll
        for (int p = 0; p < 2; p++) {
            int f4i = tid + p * 512;
            int nA  = f4i >> 6;
            int off = (f4i & 63) * 4;
            CP_ASYNC16(bufB + (nA * 256 + off) * 4,
                       &g_T[((jbA + nA) * 64 + 4 * c) * 64 + off]);
        }
        CP_COMMIT();
    };

    issue_chunk(0, 0);
    issue_chunk(1, 1);

    for (int c = 0; c < NCHUNK; c++) {
        if (c + 1 < NCHUNK) { CP_WAIT(1); } else { CP_WAIT(0); }
        __syncthreads();
        if (c + 2 < NCHUNK) issue_chunk(c + 2, (c + 2) % NSTAGE);

        const int stage = c % NSTAGE;
        const float* SA = smem + stage * BUF_WORDS;
        const float* SB = SA + A_WORDS;

        #pragma unroll
        for (int ks = 0; ks < BK_ATOMS; ks++) {
            uint32_t afr[4], bfr[4][2];
            {
                float4 v = *reinterpret_cast<const float4*>(
                    &SA[(wmA * BK_ATOMS + ks) * 128 + lane * 4]);
                afr[0] = __float_as_uint(v.x);
                afr[1] = __float_as_uint(v.y);
                afr[2] = __float_as_uint(v.z);
                afr[3] = __float_as_uint(v.w);
            }
            #pragma unroll
            for (int na = 0; na < 4; na++) {
                float2 v = *reinterpret_cast<const float2*>(
                    &SB[((wnA + na) * BK_ATOMS + ks) * 64 + lane * 2]);
                bfr[na][0] = __float_as_uint(v.x);
                bfr[na][1] = __float_as_uint(v.y);
            }
            #pragma unroll
            for (int na = 0; na < 4; na++)
                mma_tf32(d[na], afr, bfr[na]);
        }
    }

    // Epilogue: out[i,j] = -sqrt(max(d + alpha_i, 0))
    const int i0 = ib + wmA * 16 + g;
    const float al0 = g_alpha[i0];
    const float al1 = g_alpha[i0 + 8];
    #pragma unroll
    for (int na = 0; na < 4; na++) {
        const int j = jb + (wnA + na) * 8 + t * 2;
        float2 v0, v1;
        v0.x = -sqrtf(fmaxf(d[na][0] + al0, 0.0f));
        v0.y = -sqrtf(fmaxf(d[na][1] + al0, 0.0f));
        v1.x = -sqrtf(fmaxf(d[na][2] + al1, 0.0f));
        v1.y = -sqrtf(fmaxf(d[na][3] + al1, 0.0f));
        *reinterpret_cast<float2*>(&out[i0 * NNEG + j])       = v0;
        *reinterpret_cast<float2*>(&out[(i0 + 8) * NNEG + j]) = v1;
    }
}

// ---------------------------------------------------------------------------
// Launch
// ---------------------------------------------------------------------------
extern "C" void kernel_launch(void* const* d_in, const int* in_sizes, int n_in,
                              void* d_out, int out_size) {
    const float* head = (const float*)d_in[0];   // (512, 256)
    const float* tail = (const float*)d_in[1];   // (1, 2048, 256)
    const float* rel  = (const float*)d_in[2];   // (1000, 512)
    const int*   rid  = (const int*)d_in[3];     // (512,) int32 on the wire
    float* out = (float*)d_out;                  // (512, 2048)

    cudaFuncSetAttribute(pairre_mma_kernel,
                         cudaFuncAttributeMaxDynamicSharedMemorySize, SMEM_BYTES);

    prep_kernel<<<32 + NNEG / 8, 256>>>(head, tail, rel, rid);   // 288 blocks

    dim3 grid(NNEG / 128, BATCH / 64);   // (16, 8) = 128 CTAs
    pairre_mma_kernel<<<grid, 512, SMEM_BYTES>>>(out);
}